// round 5
// baseline (speedup 1.0000x reference)
#include <cuda_runtime.h>
#include <cstdint>
#include <math.h>

// Problem constants (fixed by the dataset)
#define BB 2
#define SS 2048
#define DD 512
#define HH 8
#define DH 64
#define BH (BB*HH)          // 16
#define MAXK 32
#define EPSF 1e-8f
#define SPLITK 2

// ---------------- scratch (static device globals; no allocs allowed) --------
__device__ float g_q  [BB*HH*SS*DH];              // [B,H,S,64]
__device__ float g_kT [BB*HH*DH*SS];              // [B,H,64,S]
__device__ float g_v  [BB*HH*SS*DH];              // [B,H,S,64]
__device__ float g_attn[BB*SS*DD];                // [B,S,D]
__device__ float g_part [SPLITK*BB*SS*3*DD];      // QKV split-K partials (50MB)
__device__ float g_part2[SPLITK*BB*SS*DD];        // proj split-K partials (17MB)

// ---------------- warp reduce helpers ---------------------------------------
__device__ __forceinline__ float warpMaxF(float v){
#pragma unroll
    for (int o = 16; o; o >>= 1) v = fmaxf(v, __shfl_xor_sync(0xffffffffu, v, o));
    return v;
}
__device__ __forceinline__ float warpSumF(float v){
#pragma unroll
    for (int o = 16; o; o >>= 1) v += __shfl_xor_sync(0xffffffffu, v, o);
    return v;
}
__device__ __forceinline__ unsigned warpMaxU(unsigned v){
#pragma unroll
    for (int o = 16; o; o >>= 1) { unsigned t = __shfl_xor_sync(0xffffffffu, v, o); v = t > v ? t : v; }
    return v;
}
__device__ __forceinline__ int warpSumI(int v){
#pragma unroll
    for (int o = 16; o; o >>= 1) v += __shfl_xor_sync(0xffffffffu, v, o);
    return v;
}
// monotone float -> uint mapping (descending float order == descending uint order)
__device__ __forceinline__ unsigned ordf(float f){
    unsigned u = __float_as_uint(f);
    return (u & 0x80000000u) ? ~u : (u | 0x80000000u);
}

// ---------------- split-K SGEMM: Cpart[z] = A[:,kz] * Bw[:,kz]^T -------------
// 128x128 tile, 256 threads, 8x8 thread tile, double-buffered smem.
__global__ __launch_bounds__(256, 2)
void sgemm_splitk(const float* __restrict__ A, const float* __restrict__ Bw,
                  float* __restrict__ Cpart, int M, int N, int K)
{
    const int BM = 128, BN = 128, BK = 16;
    __shared__ float As[2][BK][BM + 4];
    __shared__ float Bs[2][BK][BN + 4];

    int tid = threadIdx.x;
    int tx = tid & 15, ty = tid >> 4;
    int bm = blockIdx.y * BM, bn = blockIdx.x * BN;
    int z  = blockIdx.z;
    int kbeg = z * (K / SPLITK), kend = kbeg + (K / SPLITK);

    int lrow0 = tid >> 2,         lc0 = (tid & 3) * 4;
    int lrow1 = (tid + 256) >> 2, lc1 = lc0;

    float acc[8][8];
#pragma unroll
    for (int i = 0; i < 8; i++)
#pragma unroll
        for (int j = 0; j < 8; j++) acc[i][j] = 0.f;

    const float* Ab = A + (size_t)bm * K;
    const float* Bb = Bw + (size_t)bn * K;

    float4 pa0, pa1, pb0, pb1;
    pa0 = *(const float4*)(Ab + (size_t)lrow0 * K + kbeg + lc0);
    pa1 = *(const float4*)(Ab + (size_t)lrow1 * K + kbeg + lc1);
    pb0 = *(const float4*)(Bb + (size_t)lrow0 * K + kbeg + lc0);
    pb1 = *(const float4*)(Bb + (size_t)lrow1 * K + kbeg + lc1);
    As[0][lc0+0][lrow0]=pa0.x; As[0][lc0+1][lrow0]=pa0.y; As[0][lc0+2][lrow0]=pa0.z; As[0][lc0+3][lrow0]=pa0.w;
    As[0][lc1+0][lrow1]=pa1.x; As[0][lc1+1][lrow1]=pa1.y; As[0][lc1+2][lrow1]=pa1.z; As[0][lc1+3][lrow1]=pa1.w;
    Bs[0][lc0+0][lrow0]=pb0.x; Bs[0][lc0+1][lrow0]=pb0.y; Bs[0][lc0+2][lrow0]=pb0.z; Bs[0][lc0+3][lrow0]=pb0.w;
    Bs[0][lc1+0][lrow1]=pb1.x; Bs[0][lc1+1][lrow1]=pb1.y; Bs[0][lc1+2][lrow1]=pb1.z; Bs[0][lc1+3][lrow1]=pb1.w;
    __syncthreads();

    int it = 0;
    for (int k0 = kbeg; k0 < kend; k0 += BK, it++) {
        int buf = it & 1;
        bool more = (k0 + BK) < kend;
        if (more) {
            int kn = k0 + BK;
            pa0 = *(const float4*)(Ab + (size_t)lrow0 * K + kn + lc0);
            pa1 = *(const float4*)(Ab + (size_t)lrow1 * K + kn + lc1);
            pb0 = *(const float4*)(Bb + (size_t)lrow0 * K + kn + lc0);
            pb1 = *(const float4*)(Bb + (size_t)lrow1 * K + kn + lc1);
        }
#pragma unroll
        for (int k = 0; k < BK; k++) {
            float4 a0 = *(const float4*)&As[buf][k][ty * 8];
            float4 a1 = *(const float4*)&As[buf][k][ty * 8 + 4];
            float4 b0 = *(const float4*)&Bs[buf][k][tx * 8];
            float4 b1 = *(const float4*)&Bs[buf][k][tx * 8 + 4];
            float av[8] = {a0.x,a0.y,a0.z,a0.w,a1.x,a1.y,a1.z,a1.w};
            float bv[8] = {b0.x,b0.y,b0.z,b0.w,b1.x,b1.y,b1.z,b1.w};
#pragma unroll
            for (int i = 0; i < 8; i++)
#pragma unroll
                for (int j = 0; j < 8; j++) acc[i][j] = fmaf(av[i], bv[j], acc[i][j]);
        }
        if (more) {
            int nb = buf ^ 1;
            As[nb][lc0+0][lrow0]=pa0.x; As[nb][lc0+1][lrow0]=pa0.y; As[nb][lc0+2][lrow0]=pa0.z; As[nb][lc0+3][lrow0]=pa0.w;
            As[nb][lc1+0][lrow1]=pa1.x; As[nb][lc1+1][lrow1]=pa1.y; As[nb][lc1+2][lrow1]=pa1.z; As[nb][lc1+3][lrow1]=pa1.w;
            Bs[nb][lc0+0][lrow0]=pb0.x; Bs[nb][lc0+1][lrow0]=pb0.y; Bs[nb][lc0+2][lrow0]=pb0.z; Bs[nb][lc0+3][lrow0]=pb0.w;
            Bs[nb][lc1+0][lrow1]=pb1.x; Bs[nb][lc1+1][lrow1]=pb1.y; Bs[nb][lc1+2][lrow1]=pb1.z; Bs[nb][lc1+3][lrow1]=pb1.w;
        }
        __syncthreads();
    }

    float* Cz = Cpart + (size_t)z * M * N;
#pragma unroll
    for (int i = 0; i < 8; i++) {
        int mrow = bm + ty * 8 + i;
#pragma unroll
        for (int g = 0; g < 2; g++) {
            int col = bn + tx * 8 + g * 4;
            float4 o;
            o.x = acc[i][g*4+0]; o.y = acc[i][g*4+1];
            o.z = acc[i][g*4+2]; o.w = acc[i][g*4+3];
            *(float4*)(Cz + (size_t)mrow * N + col) = o;
        }
    }
}

// ---------------- reduce + bias + q/kT/v scatter (QKV) -----------------------
// one thread = one float4 of the [4096,1536] result.
__global__ __launch_bounds__(256)
void reduce_qkv(const float* __restrict__ bias)
{
    const int NF4 = BB*SS*3*DD/4;            // 1,572,864
    int f = blockIdx.x * 256 + threadIdx.x;
    if (f >= NF4) return;
    float4 p0 = ((const float4*)g_part)[f];
    float4 p1 = ((const float4*)g_part)[f + NF4];
    int mrow = f / (3*DD/4);                 // /384
    int n = (f - mrow * (3*DD/4)) * 4;
    float4 b4 = *(const float4*)(bias + n);
    float4 v;
    v.x = p0.x + p1.x + b4.x; v.y = p0.y + p1.y + b4.y;
    v.z = p0.z + p1.z + b4.z; v.w = p0.w + p1.w + b4.w;

    int b = mrow >> 11, s = mrow & 2047;
    int sec = n >> 9, nn = n & 511;
    int head = nn >> 6, d = nn & 63;
    if (sec == 0) {
        *(float4*)&g_q[((size_t)((b*HH+head)*SS) + s)*DH + d] = v;
    } else if (sec == 1) {
        size_t base = ((size_t)((b*HH+head)*DH) + d)*SS + s;
        g_kT[base] = v.x; g_kT[base + SS] = v.y;
        g_kT[base + 2*SS] = v.z; g_kT[base + 3*SS] = v.w;
    } else {
        *(float4*)&g_v[((size_t)((b*HH+head)*SS) + s)*DH + d] = v;
    }
}

// ---------------- reduce + bias (output projection) --------------------------
__global__ __launch_bounds__(256)
void reduce_out(const float* __restrict__ bias, float* __restrict__ out)
{
    const int NF4 = BB*SS*DD/4;              // 524,288
    int f = blockIdx.x * 256 + threadIdx.x;
    if (f >= NF4) return;
    float4 p0 = ((const float4*)g_part2)[f];
    float4 p1 = ((const float4*)g_part2)[f + NF4];
    int n = (f & (DD/4 - 1)) * 4;            // col within row (DD/4=128 f4/row)
    float4 b4 = *(const float4*)(bias + n);
    float4 v;
    v.x = p0.x + p1.x + b4.x; v.y = p0.y + p1.y + b4.y;
    v.z = p0.z + p1.z + b4.z; v.w = p0.w + p1.w + b4.w;
    ((float4*)out)[f] = v;
}

// ---------------- fused attention v3 -----------------------------------------
// TQ=16 queries/block, 512 threads. Warp w computes a 16x128 score slab and
// per-row online stats (max, Z, S1=sum p*(s-m), argmax tie count+index).
// No score buffer in smem. Combine across 16 warps; H = logZ - S1/Z.
// Fast path (H>=1.2 & unique argmax): out = V[argmax]/(1+EPS*Z).
// Exact deterministic fallback recomputes the row (bitwise-identical fmaf
// order) and runs the reference-semantics entropy/top-k.
#define TQ 16
#define ATHREADS 512

__global__ __launch_bounds__(ATHREADS, 1)
void attn_kernel()
{
    __shared__ float s_qT[DH * TQ];          // [d][i]
    __shared__ float s_ml[TQ][16];
    __shared__ float s_zl[TQ][16];
    __shared__ float s_s1[TQ][16];
    __shared__ int   s_ct[TQ][16];
    __shared__ int   s_j0[TQ][16];

    int bh = blockIdx.y;
    int q0 = blockIdx.x * TQ;
    const float* Q  = g_q  + ((size_t)bh * SS + q0) * DH;
    const float* KT = g_kT + (size_t)bh * DH * SS;
    const float* V  = g_v  + (size_t)bh * SS * DH;
    int tid = threadIdx.x, lane = tid & 31, w = tid >> 5;

    for (int e = tid; e < TQ * DH; e += ATHREADS) {
        int i = e & 15, d = e >> 4;
        s_qT[d * TQ + i] = Q[i * DH + d];
    }
    __syncthreads();

    // ---- phase 1: warp w covers cols [128w, 128w+128) for all 16 rows ------
    int c0 = w * 128 + lane * 4;
    float acc[16][4];
#pragma unroll
    for (int i = 0; i < 16; i++)
#pragma unroll
        for (int c = 0; c < 4; c++) acc[i][c] = 0.f;

#pragma unroll 4
    for (int d = 0; d < DH; d++) {
        float4 k4 = *(const float4*)(KT + (size_t)d * SS + c0);
        const float4* qp = (const float4*)(s_qT + d * TQ);   // broadcast
        float4 q4[4] = {qp[0], qp[1], qp[2], qp[3]};
        const float* qf = (const float*)q4;
#pragma unroll
        for (int i = 0; i < 16; i++) {
            float qi = qf[i];
            acc[i][0] = fmaf(qi, k4.x, acc[i][0]);
            acc[i][1] = fmaf(qi, k4.y, acc[i][1]);
            acc[i][2] = fmaf(qi, k4.z, acc[i][2]);
            acc[i][3] = fmaf(qi, k4.w, acc[i][3]);
        }
    }

    // ---- per-row slab stats ------------------------------------------------
    const float scale = 0.125f;
#pragma unroll
    for (int i = 0; i < 16; i++) {
        float v0 = acc[i][0]*scale, v1 = acc[i][1]*scale,
              v2 = acc[i][2]*scale, v3 = acc[i][3]*scale;
        float ml = fmaxf(fmaxf(v0, v1), fmaxf(v2, v3));
        ml = warpMaxF(ml);
        float e0 = expf(v0-ml), e1 = expf(v1-ml), e2 = expf(v2-ml), e3 = expf(v3-ml);
        float zl  = (e0+e1) + (e2+e3);
        float s1l = fmaf(e0, v0-ml, fmaf(e1, v1-ml, fmaf(e2, v2-ml, e3*(v3-ml))));
        zl  = warpSumF(zl);
        s1l = warpSumF(s1l);
        int lc = (v0==ml) + (v1==ml) + (v2==ml) + (v3==ml);
        int li = (v0==ml) ? c0 : (v1==ml) ? c0+1 : (v2==ml) ? c0+2 : c0+3;
        int ct = warpSumI(lc);
        unsigned msk = __ballot_sync(0xffffffffu, lc > 0);
        int src = __ffs((int)msk) - 1;
        int j0 = __shfl_sync(0xffffffffu, li, src);
        if (lane == 0) {
            s_ml[i][w] = ml; s_zl[i][w] = zl; s_s1[i][w] = s1l;
            s_ct[i][w] = ct; s_j0[i][w] = j0;
        }
    }
    __syncthreads();

    // ---- combine: warp w owns row w ----------------------------------------
    bool act = lane < 16;
    float mlv = act ? s_ml[w][lane] : -3.0e38f;
    float m = warpMaxF(mlv);
    float zlv = act ? s_zl[w][lane] : 0.f;
    float r = act ? expf(mlv - m) : 0.f;
    float z  = warpSumF(r * zlv);
    float s1 = warpSumF(act ? r * fmaf(mlv - m, zlv, s_s1[w][lane]) : 0.f);
    float hent = logf(z) - s1 / z;
    int ctv = (act && mlv == m) ? s_ct[w][lane] : 0;
    int cnt = warpSumI(ctv);
    unsigned msk = __ballot_sync(0xffffffffu, ctv > 0);
    int src = __ffs((int)msk) - 1;
    int j0 = __shfl_sync(0xffffffffu, act ? s_j0[w][lane] : 0, src);

    int b = bh >> 3, hd = bh & 7;
    float* outp = &g_attn[((size_t)(b * SS + q0 + w)) * DD + hd * DH + lane * 2];

    if (hent >= 1.2f && cnt == 1) {
        // tk = 1 (32*(1-H) < -6), unique argmax: p = 1, P = 1.
        float wgt = 1.0f / (1.0f + EPSF * z);
        float2 vv = *(const float2*)(V + (size_t)j0 * DH + lane * 2);
        float2 o; o.x = vv.x * wgt; o.y = vv.y * wgt;
        *(float2*)outp = o;
    } else {
        // ---- exact deterministic fallback (rare) ---------------------------
        float fb[64];
        for (int jj = 0; jj < 64; jj++) {
            int j = lane + (jj << 5);
            float s = 0.f;
            for (int d = 0; d < DH; d++)
                s = fmaf(s_qT[d * TQ + w], KT[(size_t)d * SS + j], s);
            fb[jj] = s * scale;
        }
        float m2 = -3.0e38f;
        for (int jj = 0; jj < 64; jj++) m2 = fmaxf(m2, fb[jj]);
        m2 = warpMaxF(m2);
        float z2 = 0.f;
        for (int jj = 0; jj < 64; jj++) z2 += expf(fb[jj] - m2);
        z2 = warpSumF(z2);
        float invZ = 1.0f / z2;
        float he = 0.f;
        for (int jj = 0; jj < 64; jj++) {
            float p  = expf(fb[jj] - m2);
            float ww = p * invZ;
            he -= ww * logf(ww + EPSF);
        }
        he = warpSumF(he);
        int tk = (int)(32.0f * (1.0f - he));
        tk = tk < 1 ? 1 : (tk > MAXK ? MAXK : tk);

        unsigned thr_u;
        if (tk == 1) {
            thr_u = ordf(m2);
        } else {
            thr_u = 0xFFFFFFFFu;
            int removed = 0;
            while (removed < tk) {
                unsigned best = 0u;
                for (int jj = 0; jj < 64; jj++) {
                    unsigned u = ordf(fb[jj]);
                    if (u < thr_u && u > best) best = u;
                }
                best = warpMaxU(best);
                int c = 0;
                for (int jj = 0; jj < 64; jj++) c += (ordf(fb[jj]) == best);
                c = warpSumI(c);
                removed += c;
                thr_u = best;
            }
        }

        float P = 0.f;
        for (int jj = 0; jj < 64; jj++)
            if (ordf(fb[jj]) >= thr_u) P += expf(fb[jj] - m2);
        P = warpSumF(P);
        float invDen = 1.0f / (P + EPSF * z2);

        // per-dim-pair accumulation, fixed order => deterministic
        float r0 = 0.f, r1 = 0.f;
        for (int d0 = 0; d0 < DH; d0 += 2) {
            float a0 = 0.f, a1 = 0.f;
            for (int jj = 0; jj < 64; jj++) {
                float s = fb[jj];
                if (ordf(s) >= thr_u) {
                    int j = lane + (jj << 5);
                    float p = expf(s - m2);
                    float2 vv = *(const float2*)(V + (size_t)j * DH + d0);
                    a0 = fmaf(p, vv.x, a0);
                    a1 = fmaf(p, vv.y, a1);
                }
            }
            a0 = warpSumF(a0);
            a1 = warpSumF(a1);
            if (lane == (d0 >> 1)) { r0 = a0; r1 = a1; }
        }
        float2 o; o.x = r0 * invDen; o.y = r1 * invDen;
        *(float2*)outp = o;
    }
}

// ---------------- launch -----------------------------------------------------
extern "C" void kernel_launch(void* const* d_in, const int* in_sizes, int n_in,
                              void* d_out, int out_size)
{
    const float* x     = (const float*)d_in[0];
    const float* w_in  = (const float*)d_in[1];
    const float* b_in  = (const float*)d_in[2];
    const float* w_out = (const float*)d_in[3];
    const float* b_out = (const float*)d_in[4];
    float* out = (float*)d_out;

    float *pattn = nullptr, *ppart = nullptr, *ppart2 = nullptr;
    cudaGetSymbolAddress((void**)&pattn,  g_attn);
    cudaGetSymbolAddress((void**)&ppart,  g_part);
    cudaGetSymbolAddress((void**)&ppart2, g_part2);

    // 1) QKV projection, split-K=2
    sgemm_splitk<<<dim3((3*DD)/128, (BB*SS)/128, SPLITK), 256>>>(
        x, w_in, ppart, BB*SS, 3*DD, DD);
    reduce_qkv<<<(BB*SS*3*DD/4 + 255)/256, 256>>>(b_in);

    // 2) fused attention + entropy top-k
    attn_kernel<<<dim3(SS/TQ, BH), ATHREADS>>>();

    // 3) output projection, split-K=2
    sgemm_splitk<<<dim3(DD/128, (BB*SS)/128, SPLITK), 256>>>(
        pattn, w_out, ppart2, BB*SS, DD, DD);
    reduce_out<<<(BB*SS*DD/4 + 255)/256, 256>>>(b_out, out);
}